// round 2
// baseline (speedup 1.0000x reference)
#include <cuda_runtime.h>

#define T_DIM   32
#define N_NODES 10000
#define E_EDGES 160000
#define F_DIM   64
#define TN      (T_DIM * N_NODES)

// -------- device scratch (allocation-free rule: __device__ globals) --------
__device__ int   g_i64flag;                          // 1 = edge_index is int64
__device__ float g_deg[N_NODES];
__device__ float g_dinv[N_NODES];
__device__ int   g_count[N_NODES];
__device__ int   g_rowoff[N_NODES + 1];
__device__ int   g_cursor[N_NODES];
__device__ int2  g_csr[E_EDGES];                     // {src, norm_as_int}
__device__ float g_bufA[(size_t)TN * F_DIM];         // 81.92 MB
__device__ float g_bufB[(size_t)TN * F_DIM];         // 81.92 MB

// Decode edge endpoints regardless of on-device dtype (int32 vs int64).
__device__ __forceinline__ int edge_src(const void* ei, int e) {
    return g_i64flag ? (int)((const long long*)ei)[e] : ((const int*)ei)[e];
}
__device__ __forceinline__ int edge_dst(const void* ei, int e) {
    return g_i64flag ? (int)((const long long*)ei)[E_EDGES + e]
                     : ((const int*)ei)[E_EDGES + e];
}

// -------- prep kernels --------
__global__ void k_init() {
    int i = blockIdx.x * blockDim.x + threadIdx.x;
    if (i == 0) g_i64flag = 1;
    if (i < N_NODES) { g_deg[i] = 0.f; g_count[i] = 0; }
}

// Read first E entries as int64 (in-bounds for either dtype: int32 buffer is
// exactly 8E bytes). If data is really int32, entry e = lo|hi<<32 with hi a
// random node id -> out of [0,N) with overwhelming probability somewhere.
__global__ void k_detect(const void* __restrict__ ei) {
    int e = blockIdx.x * blockDim.x + threadIdx.x;
    if (e < E_EDGES) {
        long long v = ((const long long*)ei)[e];
        if (v < 0 || v >= N_NODES) g_i64flag = 0;   // racy but all writers write 0
    }
}

__global__ void k_hist(const void* __restrict__ ei, const float* __restrict__ ew) {
    int e = blockIdx.x * blockDim.x + threadIdx.x;
    if (e < E_EDGES) {
        int dst = edge_dst(ei, e);
        atomicAdd(&g_deg[dst], ew[e]);
        atomicAdd(&g_count[dst], 1);
    }
}

__global__ void k_dinv() {
    int i = blockIdx.x * blockDim.x + threadIdx.x;
    if (i < N_NODES) {
        float d = g_deg[i];
        g_dinv[i] = (d > 0.f) ? rsqrtf(d) : 0.f;
    }
}

// single-block exclusive scan of g_count -> g_rowoff (+ cursor copy)
__global__ void k_scan() {
    __shared__ int s[1024];
    const int tid = threadIdx.x;
    const int CH  = (N_NODES + 1023) / 1024;   // 10
    int base = tid * CH;
    int sum = 0;
    for (int i = 0; i < CH; i++) {
        int idx = base + i;
        if (idx < N_NODES) sum += g_count[idx];
    }
    s[tid] = sum;
    __syncthreads();
    for (int off = 1; off < 1024; off <<= 1) {
        int v   = s[tid];
        int add = (tid >= off) ? s[tid - off] : 0;
        __syncthreads();
        s[tid] = v + add;
        __syncthreads();
    }
    int prefix = (tid == 0) ? 0 : s[tid - 1];
    for (int i = 0; i < CH; i++) {
        int idx = base + i;
        if (idx < N_NODES) {
            g_rowoff[idx] = prefix;
            g_cursor[idx] = prefix;
            prefix += g_count[idx];
        }
    }
    if (tid == 1023) g_rowoff[N_NODES] = s[1023];
}

__global__ void k_fill(const void* __restrict__ ei, const float* __restrict__ ew) {
    int e = blockIdx.x * blockDim.x + threadIdx.x;
    if (e < E_EDGES) {
        int src = edge_src(ei, e);
        int dst = edge_dst(ei, e);
        float nm = g_dinv[src] * ew[e] * g_dinv[dst];
        int pos = atomicAdd(&g_cursor[dst], 1);
        g_csr[pos] = make_int2(src, __float_as_int(nm));
    }
}

// -------- aggregation: one warp per (node, t); pull over CSR, no atomics --------
__global__ void __launch_bounds__(256) k_agg(const float* __restrict__ in,
                                             float* __restrict__ out) {
    int wg   = (blockIdx.x * blockDim.x + threadIdx.x) >> 5;
    int lane = threadIdx.x & 31;
    if (wg >= TN) return;
    int node = wg >> 5;       // T_DIM == 32
    int t    = wg & 31;

    int beg = g_rowoff[node];
    int end = g_rowoff[node + 1];

    const float* base = in + (size_t)t * (N_NODES * F_DIM) + lane * 2;
    float2 acc = make_float2(0.f, 0.f);

    int e = beg;
    for (; e + 1 < end; e += 2) {
        int2 sn0 = __ldg(&g_csr[e]);
        int2 sn1 = __ldg(&g_csr[e + 1]);
        float2 v0 = __ldg((const float2*)(base + (size_t)sn0.x * F_DIM));
        float2 v1 = __ldg((const float2*)(base + (size_t)sn1.x * F_DIM));
        float w0 = __int_as_float(sn0.y);
        float w1 = __int_as_float(sn1.y);
        acc.x = fmaf(w0, v0.x, acc.x);
        acc.y = fmaf(w0, v0.y, acc.y);
        acc.x = fmaf(w1, v1.x, acc.x);
        acc.y = fmaf(w1, v1.y, acc.y);
    }
    if (e < end) {
        int2 sn = __ldg(&g_csr[e]);
        float2 v = __ldg((const float2*)(base + (size_t)sn.x * F_DIM));
        float w = __int_as_float(sn.y);
        acc.x = fmaf(w, v.x, acc.x);
        acc.y = fmaf(w, v.y, acc.y);
    }

    float* op = out + (size_t)t * (N_NODES * F_DIM) + (size_t)node * F_DIM + lane * 2;
    *((float2*)op) = acc;
}

// -------- GEMM: [M x 64] * [64 x 64] + bias (+relu). 128 rows/block, 8x8/thread --------
__global__ void __launch_bounds__(128) k_gemm(const float* __restrict__ A,
                                              const float* __restrict__ W,
                                              const float* __restrict__ bias,
                                              float* __restrict__ Out,
                                              int do_relu) {
    __shared__ float xs[128][F_DIM];   // 32 KB
    __shared__ float ws[F_DIM][F_DIM]; // 16 KB
    const int tid  = threadIdx.x;
    const size_t row0 = (size_t)blockIdx.x * 128;

    for (int i = tid; i < F_DIM * F_DIM / 4; i += 128)
        ((float4*)ws)[i] = ((const float4*)W)[i];
    {
        const float4* Ag  = (const float4*)(A + row0 * F_DIM);
        float4*       xs4 = (float4*)xs;
        #pragma unroll
        for (int i = 0; i < 16; i++)
            xs4[tid + i * 128] = Ag[tid + i * 128];
    }
    __syncthreads();

    const int tx = tid & 7, ty = tid >> 3;
    const int r0 = ty * 8, c0 = tx * 8;

    float acc[8][8];
    #pragma unroll
    for (int i = 0; i < 8; i++)
        #pragma unroll
        for (int j = 0; j < 8; j++) acc[i][j] = 0.f;

    #pragma unroll 8
    for (int k = 0; k < F_DIM; k++) {
        float a[8], b[8];
        #pragma unroll
        for (int i = 0; i < 8; i++) a[i] = xs[r0 + i][k];
        float4 b0 = *(const float4*)&ws[k][c0];
        float4 b1 = *(const float4*)&ws[k][c0 + 4];
        b[0] = b0.x; b[1] = b0.y; b[2] = b0.z; b[3] = b0.w;
        b[4] = b1.x; b[5] = b1.y; b[6] = b1.z; b[7] = b1.w;
        #pragma unroll
        for (int i = 0; i < 8; i++)
            #pragma unroll
            for (int j = 0; j < 8; j++)
                acc[i][j] = fmaf(a[i], b[j], acc[i][j]);
    }

    float bb[8];
    #pragma unroll
    for (int j = 0; j < 8; j++) bb[j] = bias[c0 + j];

    #pragma unroll
    for (int i = 0; i < 8; i++) {
        float o[8];
        #pragma unroll
        for (int j = 0; j < 8; j++) {
            float v = acc[i][j] + bb[j];
            o[j] = do_relu ? fmaxf(v, 0.f) : v;
        }
        float4* p = (float4*)(Out + (row0 + r0 + i) * F_DIM + c0);
        p[0] = make_float4(o[0], o[1], o[2], o[3]);
        p[1] = make_float4(o[4], o[5], o[6], o[7]);
    }
}

// -------- launch --------
extern "C" void kernel_launch(void* const* d_in, const int* in_sizes, int n_in,
                              void* d_out, int out_size) {
    const float* x   = (const float*)d_in[0];
    const void*  ei  = d_in[1];
    const float* ew  = (const float*)d_in[2];
    const float* W1  = (const float*)d_in[3];
    const float* b1  = (const float*)d_in[4];
    const float* W2  = (const float*)d_in[5];
    const float* b2  = (const float*)d_in[6];
    float*       out = (float*)d_out;

    float *bufA = nullptr, *bufB = nullptr;
    cudaGetSymbolAddress((void**)&bufA, g_bufA);
    cudaGetSymbolAddress((void**)&bufB, g_bufB);

    k_init  <<<(N_NODES + 255) / 256, 256>>>();
    k_detect<<<(E_EDGES + 255) / 256, 256>>>(ei);
    k_hist  <<<(E_EDGES + 255) / 256, 256>>>(ei, ew);
    k_dinv  <<<(N_NODES + 255) / 256, 256>>>();
    k_scan  <<<1, 1024>>>();
    k_fill  <<<(E_EDGES + 255) / 256, 256>>>(ei, ew);

    // layer 1: out1 = relu((A x) W1 + b1)
    k_agg <<<TN / 8, 256>>>(x, bufA);
    k_gemm<<<TN / 128, 128>>>(bufA, W1, b1, bufB, 1);
    // layer 2: out = (A out1) W2 + b2
    k_agg <<<TN / 8, 256>>>(bufB, bufA);
    k_gemm<<<TN / 128, 128>>>(bufA, W2, b2, out, 0);
}

// round 3
// speedup vs baseline: 1.1812x; 1.1812x over previous
#include <cuda_runtime.h>

#define T_DIM   32
#define N_NODES 10000
#define E_EDGES 160000
#define F_DIM   64
#define TN      (T_DIM * N_NODES)

typedef unsigned long long ull;

// ---- packed f32x2 helpers (FFMA2 is PTX-only; ptxas never auto-fuses) ----
__device__ __forceinline__ ull pack2(float lo, float hi) {
    ull r; asm("mov.b64 %0, {%1, %2};" : "=l"(r) : "f"(lo), "f"(hi)); return r;
}
__device__ __forceinline__ float2 unpack2(ull v) {
    float2 r; asm("mov.b64 {%0, %1}, %2;" : "=f"(r.x), "=f"(r.y) : "l"(v)); return r;
}
__device__ __forceinline__ ull fma2(ull a, ull b, ull c) {
    ull d; asm("fma.rn.f32x2 %0, %1, %2, %3;" : "=l"(d) : "l"(a), "l"(b), "l"(c)); return d;
}
__device__ __forceinline__ ull add2(ull a, ull b) {
    ull d; asm("add.rn.f32x2 %0, %1, %2;" : "=l"(d) : "l"(a), "l"(b)); return d;
}

// -------- device scratch (allocation-free rule: __device__ globals) --------
__device__ int   g_i64flag;                          // 1 = edge_index is int64
__device__ float g_deg[N_NODES];
__device__ float g_dinv[N_NODES];
__device__ int   g_count[N_NODES];
__device__ int   g_rowoff[N_NODES + 1];
__device__ int   g_cursor[N_NODES];
__device__ int2  g_csr[E_EDGES];                     // {src, norm_as_int}
__device__ float g_bufA[(size_t)TN * F_DIM];         // 81.92 MB
__device__ float g_bufB[(size_t)TN * F_DIM];         // 81.92 MB

__device__ __forceinline__ int edge_src(const void* ei, int e) {
    return g_i64flag ? (int)((const long long*)ei)[e] : ((const int*)ei)[e];
}
__device__ __forceinline__ int edge_dst(const void* ei, int e) {
    return g_i64flag ? (int)((const long long*)ei)[E_EDGES + e]
                     : ((const int*)ei)[E_EDGES + e];
}

// -------- prep kernels --------
__global__ void k_init() {
    int i = blockIdx.x * blockDim.x + threadIdx.x;
    if (i == 0) g_i64flag = 1;
    if (i < N_NODES) { g_deg[i] = 0.f; g_count[i] = 0; }
}

// In-bounds for either dtype (int32 buffer is exactly 8E bytes when read as E int64).
__global__ void k_detect(const void* __restrict__ ei) {
    int e = blockIdx.x * blockDim.x + threadIdx.x;
    if (e < E_EDGES) {
        long long v = ((const long long*)ei)[e];
        if (v < 0 || v >= N_NODES) g_i64flag = 0;
    }
}

__global__ void k_hist(const void* __restrict__ ei, const float* __restrict__ ew) {
    int e = blockIdx.x * blockDim.x + threadIdx.x;
    if (e < E_EDGES) {
        int dst = edge_dst(ei, e);
        atomicAdd(&g_deg[dst], ew[e]);
        atomicAdd(&g_count[dst], 1);
    }
}

// dinv + single-block exclusive scan (count -> rowoff, cursor)
__global__ void k_scandinv() {
    __shared__ int s[1024];
    const int tid = threadIdx.x;
    const int CH  = (N_NODES + 1023) / 1024;   // 10
    int base = tid * CH;
    int sum = 0;
    for (int i = 0; i < CH; i++) {
        int idx = base + i;
        if (idx < N_NODES) {
            float d = g_deg[idx];
            g_dinv[idx] = (d > 0.f) ? rsqrtf(d) : 0.f;
            sum += g_count[idx];
        }
    }
    s[tid] = sum;
    __syncthreads();
    for (int off = 1; off < 1024; off <<= 1) {
        int v   = s[tid];
        int add = (tid >= off) ? s[tid - off] : 0;
        __syncthreads();
        s[tid] = v + add;
        __syncthreads();
    }
    int prefix = (tid == 0) ? 0 : s[tid - 1];
    for (int i = 0; i < CH; i++) {
        int idx = base + i;
        if (idx < N_NODES) {
            g_rowoff[idx] = prefix;
            g_cursor[idx] = prefix;
            prefix += g_count[idx];
        }
    }
    if (tid == 1023) g_rowoff[N_NODES] = s[1023];
}

__global__ void k_fill(const void* __restrict__ ei, const float* __restrict__ ew) {
    int e = blockIdx.x * blockDim.x + threadIdx.x;
    if (e < E_EDGES) {
        int src = edge_src(ei, e);
        int dst = edge_dst(ei, e);
        float nm = g_dinv[src] * ew[e] * g_dinv[dst];
        int pos = atomicAdd(&g_cursor[dst], 1);
        g_csr[pos] = make_int2(src, __float_as_int(nm));
    }
}

// -------- aggregation: one warp per (t, node), t-MAJOR so the active gather
// window is one 2.56 MB t-slice (L2-resident). Pull over CSR, no atomics. --------
__global__ void __launch_bounds__(256) k_agg(const float* __restrict__ in,
                                             float* __restrict__ out) {
    int wg   = (blockIdx.x * blockDim.x + threadIdx.x) >> 5;
    int lane = threadIdx.x & 31;
    if (wg >= TN) return;
    int t    = wg / N_NODES;
    int node = wg - t * N_NODES;

    int beg = g_rowoff[node];
    int end = g_rowoff[node + 1];

    const ull* base = (const ull*)(in + (size_t)t * (N_NODES * F_DIM));
    ull acc0 = 0ull, acc1 = 0ull;   // bits of (0.f, 0.f)

    int e = beg;
    for (; e + 3 < end; e += 4) {
        int2 s0 = __ldg(&g_csr[e]);
        int2 s1 = __ldg(&g_csr[e + 1]);
        int2 s2 = __ldg(&g_csr[e + 2]);
        int2 s3 = __ldg(&g_csr[e + 3]);
        ull v0 = __ldg(base + (size_t)s0.x * 32 + lane);
        ull v1 = __ldg(base + (size_t)s1.x * 32 + lane);
        ull v2 = __ldg(base + (size_t)s2.x * 32 + lane);
        ull v3 = __ldg(base + (size_t)s3.x * 32 + lane);
        float w0 = __int_as_float(s0.y), w1 = __int_as_float(s1.y);
        float w2 = __int_as_float(s2.y), w3 = __int_as_float(s3.y);
        acc0 = fma2(pack2(w0, w0), v0, acc0);
        acc1 = fma2(pack2(w1, w1), v1, acc1);
        acc0 = fma2(pack2(w2, w2), v2, acc0);
        acc1 = fma2(pack2(w3, w3), v3, acc1);
    }
    for (; e < end; e++) {
        int2 sn = __ldg(&g_csr[e]);
        ull v = __ldg(base + (size_t)sn.x * 32 + lane);
        float w = __int_as_float(sn.y);
        acc0 = fma2(pack2(w, w), v, acc0);
    }

    float2 a = unpack2(acc0), b = unpack2(acc1);
    float2 r = make_float2(a.x + b.x, a.y + b.y);
    // out[t][node] row: offset = wg * 64 (t-major contiguous)
    ((float2*)(out + (size_t)wg * F_DIM))[lane] = r;
}

// -------- GEMM: [M x 64] * [64 x 64] + bias (+relu), FFMA2-packed.
// 128 rows/block, 8x8 register tile per thread (4 f32x2 pairs wide). --------
__global__ void __launch_bounds__(128) k_gemm(const float* __restrict__ A,
                                              const float* __restrict__ W,
                                              const float* __restrict__ bias,
                                              float* __restrict__ Out,
                                              int do_relu) {
    __shared__ float xs[128][F_DIM];   // 32 KB
    __shared__ float ws[F_DIM][F_DIM]; // 16 KB
    const int tid  = threadIdx.x;
    const size_t row0 = (size_t)blockIdx.x * 128;

    for (int i = tid; i < F_DIM * F_DIM / 4; i += 128)
        ((float4*)ws)[i] = ((const float4*)W)[i];
    {
        const float4* Ag  = (const float4*)(A + row0 * F_DIM);
        float4*       xs4 = (float4*)xs;
        #pragma unroll
        for (int i = 0; i < 16; i++)
            xs4[tid + i * 128] = Ag[tid + i * 128];
    }
    __syncthreads();

    const int tx = tid & 7, ty = tid >> 3;
    const int r0 = ty * 8, c0 = tx * 8;

    ull acc[8][4];
    #pragma unroll
    for (int i = 0; i < 8; i++)
        #pragma unroll
        for (int j = 0; j < 4; j++) acc[i][j] = 0ull;

    #pragma unroll
    for (int k4 = 0; k4 < F_DIM / 4; k4++) {
        float4 a4[8];
        #pragma unroll
        for (int i = 0; i < 8; i++)
            a4[i] = *(const float4*)&xs[r0 + i][k4 * 4];
        #pragma unroll
        for (int kk = 0; kk < 4; kk++) {
            const int k = k4 * 4 + kk;
            const ull* wr = (const ull*)&ws[k][c0];
            ull b0 = wr[0], b1 = wr[1], b2 = wr[2], b3 = wr[3];
            #pragma unroll
            for (int i = 0; i < 8; i++) {
                float a = (kk == 0) ? a4[i].x : (kk == 1) ? a4[i].y
                        : (kk == 2) ? a4[i].z : a4[i].w;
                ull pa = pack2(a, a);
                acc[i][0] = fma2(pa, b0, acc[i][0]);
                acc[i][1] = fma2(pa, b1, acc[i][1]);
                acc[i][2] = fma2(pa, b2, acc[i][2]);
                acc[i][3] = fma2(pa, b3, acc[i][3]);
            }
        }
    }

    ull bb[4];
    #pragma unroll
    for (int jp = 0; jp < 4; jp++)
        bb[jp] = *((const ull*)(bias + c0) + jp);

    #pragma unroll
    for (int i = 0; i < 8; i++) {
        float o[8];
        #pragma unroll
        for (int jp = 0; jp < 4; jp++) {
            float2 v = unpack2(add2(acc[i][jp], bb[jp]));
            o[jp * 2]     = do_relu ? fmaxf(v.x, 0.f) : v.x;
            o[jp * 2 + 1] = do_relu ? fmaxf(v.y, 0.f) : v.y;
        }
        float4* p = (float4*)(Out + (row0 + r0 + i) * F_DIM + c0);
        p[0] = make_float4(o[0], o[1], o[2], o[3]);
        p[1] = make_float4(o[4], o[5], o[6], o[7]);
    }
}

// -------- launch (launch #5 == first k_agg, for ncu -s 5 -c 1 attribution) --------
extern "C" void kernel_launch(void* const* d_in, const int* in_sizes, int n_in,
                              void* d_out, int out_size) {
    const float* x   = (const float*)d_in[0];
    const void*  ei  = d_in[1];
    const float* ew  = (const float*)d_in[2];
    const float* W1  = (const float*)d_in[3];
    const float* b1  = (const float*)d_in[4];
    const float* W2  = (const float*)d_in[5];
    const float* b2  = (const float*)d_in[6];
    float*       out = (float*)d_out;

    float *bufA = nullptr, *bufB = nullptr;
    cudaGetSymbolAddress((void**)&bufA, g_bufA);
    cudaGetSymbolAddress((void**)&bufB, g_bufB);

    k_init    <<<(N_NODES + 255) / 256, 256>>>();            // 0
    k_detect  <<<(E_EDGES + 255) / 256, 256>>>(ei);          // 1
    k_hist    <<<(E_EDGES + 255) / 256, 256>>>(ei, ew);      // 2
    k_scandinv<<<1, 1024>>>();                               // 3
    k_fill    <<<(E_EDGES + 255) / 256, 256>>>(ei, ew);      // 4

    // layer 1: out1 = relu((A x) W1 + b1)
    k_agg <<<TN / 8, 256>>>(x, bufA);                        // 5  (ncu target)
    k_gemm<<<TN / 128, 128>>>(bufA, W1, b1, bufB, 1);        // 6
    // layer 2: out = (A out1) W2 + b2
    k_agg <<<TN / 8, 256>>>(bufB, bufA);                     // 7
    k_gemm<<<TN / 128, 128>>>(bufA, W2, b2, out, 0);         // 8
}